// round 1
// baseline (speedup 1.0000x reference)
#include <cuda_runtime.h>
#include <math.h>

#define NN 50000
#define EE 800000
#define HH 128
#define SS 5000
#define GG 64

// Scratch (device globals: no allocation allowed in kernel_launch)
__device__ float g_h   [NN*HH];
__device__ float g_h2  [NN*HH];
__device__ float g_aggr[NN*HH];
__device__ float g_sub [SS*HH];
__device__ float g_graph[GG*HH];

// ---------------------------------------------------------------------------
__global__ void copy_f4(const float4* __restrict__ s, float4* __restrict__ d, int n4) {
    int i = blockIdx.x * blockDim.x + threadIdx.x;
    if (i < n4) d[i] = s[i];
}

__global__ void zero_f4(float4* __restrict__ d, int n4) {
    int i = blockIdx.x * blockDim.x + threadIdx.x;
    if (i < n4) d[i] = make_float4(0.f, 0.f, 0.f, 0.f);
}

// conv1 aggregation: F_IN = 2 features per edge. aggr pre-initialized with x.
__global__ void edge_aggr2(const int* __restrict__ src, const int* __restrict__ dst,
                           const float* __restrict__ x, float* __restrict__ aggr) {
    int e = blockIdx.x * blockDim.x + threadIdx.x;
    if (e >= EE) return;
    int s = src[e], d = dst[e];
    float2 v = *(const float2*)(x + 2 * s);
    atomicAdd(&aggr[2 * d],     v.x);
    atomicAdd(&aggr[2 * d + 1], v.y);
}

// H=128 aggregation: one warp per edge, each lane handles 4 contiguous floats.
// aggr is pre-initialized with h, so after this pass aggr = h + sum_{src->dst} h[src].
__global__ void edge_aggr128(const int* __restrict__ src, const int* __restrict__ dst,
                             const float* __restrict__ h, float* __restrict__ aggr) {
    unsigned t = blockIdx.x * blockDim.x + threadIdx.x;
    unsigned e = t >> 5;
    if (e >= EE) return;
    int lane = (int)(t & 31);
    int s = src[e], d = dst[e];
    float4 v = *(const float4*)(h + s * HH + lane * 4);
    float* o = aggr + d * HH + lane * 4;
    atomicAdd(o + 0, v.x);
    atomicAdd(o + 1, v.y);
    atomicAdd(o + 2, v.z);
    atomicAdd(o + 3, v.w);
}

// conv1 first linear: (N,2) @ (2,128) + b, relu. One thread per output element.
__global__ void conv1_lin(const float* __restrict__ aggr2, const float* __restrict__ W1a,
                          const float* __restrict__ b1a, float* __restrict__ out) {
    int idx = blockIdx.x * blockDim.x + threadIdx.x;
    if (idx >= NN * HH) return;
    int n = idx >> 7, j = idx & 127;
    float a0 = aggr2[2 * n], a1 = aggr2[2 * n + 1];
    float v = fmaf(a0, W1a[j], fmaf(a1, W1a[HH + j], b1a[j]));
    out[idx] = fmaxf(v, 0.f);
}

// C[N,128] = relu(A[N,128] @ W[128,128] + bias)
// Block: 256 threads, computes a 64-row x 128-col tile; thread = 4 rows x 8 cols.
__global__ void gemm_relu(const float* __restrict__ A, const float* __restrict__ W,
                          const float* __restrict__ bias, float* __restrict__ C) {
    __shared__ float As[16][64];    // A tile, transposed: As[k][row]
    __shared__ float Ws[16][128];   // W tile: Ws[k][col]

    const int tid = threadIdx.x;
    const int tx  = tid & 15;   // col group: cols tx*8 .. tx*8+7
    const int ty  = tid >> 4;   // row group: rows ty*4 .. ty*4+3
    const int rowBase = blockIdx.x * 64;

    float acc[4][8];
#pragma unroll
    for (int i = 0; i < 4; i++)
#pragma unroll
        for (int j = 0; j < 8; j++) acc[i][j] = 0.f;

    const int lr = tid >> 2;         // 0..63: row for A-tile load
    const int lk = (tid & 3) * 4;    // k offset within chunk
    const int wk = tid >> 5;         // 0..7: W-tile row
    const int wj = (tid & 31) * 4;   // W-tile col

    for (int k0 = 0; k0 < HH; k0 += 16) {
        float4 av = make_float4(0.f, 0.f, 0.f, 0.f);
        int grow = rowBase + lr;
        if (grow < NN) av = *(const float4*)(A + grow * HH + k0 + lk);
        As[lk + 0][lr] = av.x;
        As[lk + 1][lr] = av.y;
        As[lk + 2][lr] = av.z;
        As[lk + 3][lr] = av.w;

        *(float4*)&Ws[wk][wj]     = *(const float4*)(W + (k0 + wk) * HH + wj);
        *(float4*)&Ws[wk + 8][wj] = *(const float4*)(W + (k0 + wk + 8) * HH + wj);
        __syncthreads();

#pragma unroll
        for (int kk = 0; kk < 16; kk++) {
            float4 a  = *(const float4*)&As[kk][ty * 4];
            float4 w0 = *(const float4*)&Ws[kk][tx * 8];
            float4 w1 = *(const float4*)&Ws[kk][tx * 8 + 4];
            float aa[4] = {a.x, a.y, a.z, a.w};
            float ww[8] = {w0.x, w0.y, w0.z, w0.w, w1.x, w1.y, w1.z, w1.w};
#pragma unroll
            for (int i = 0; i < 4; i++)
#pragma unroll
                for (int j = 0; j < 8; j++)
                    acc[i][j] = fmaf(aa[i], ww[j], acc[i][j]);
        }
        __syncthreads();
    }

    float4 b0 = *(const float4*)(bias + tx * 8);
    float4 b1 = *(const float4*)(bias + tx * 8 + 4);
    float bb[8] = {b0.x, b0.y, b0.z, b0.w, b1.x, b1.y, b1.z, b1.w};
#pragma unroll
    for (int i = 0; i < 4; i++) {
        int row = rowBase + ty * 4 + i;
        if (row < NN) {
            float o[8];
#pragma unroll
            for (int j = 0; j < 8; j++) o[j] = fmaxf(acc[i][j] + bb[j], 0.f);
            *(float4*)(C + row * HH + tx * 8)     = make_float4(o[0], o[1], o[2], o[3]);
            *(float4*)(C + row * HH + tx * 8 + 4) = make_float4(o[4], o[5], o[6], o[7]);
        }
    }
}

// Segment-sum scatter: one warp per input row, 4 floats per lane.
__global__ void pool_scatter(const float* __restrict__ h, const int* __restrict__ seg,
                             float* __restrict__ out, int n) {
    unsigned t = blockIdx.x * blockDim.x + threadIdx.x;
    unsigned i = t >> 5;
    if (i >= (unsigned)n) return;
    int lane = (int)(t & 31);
    int sg = seg[i];
    float4 v = *(const float4*)(h + i * HH + lane * 4);
    float* o = out + sg * HH + lane * 4;
    atomicAdd(o + 0, v.x);
    atomicAdd(o + 1, v.y);
    atomicAdd(o + 2, v.z);
    atomicAdd(o + 3, v.w);
}

// Head: per-graph MLP + log_softmax. One block per graph, 128 threads.
__global__ void head(const float* __restrict__ graph, const float* __restrict__ l1W,
                     const float* __restrict__ l1b, const float* __restrict__ l2W,
                     const float* __restrict__ l2b, float* __restrict__ out) {
    __shared__ float row[HH];
    __shared__ float h1[HH];
    __shared__ float red[HH];
    int g = blockIdx.x;
    int j = threadIdx.x;

    row[j] = graph[g * HH + j];
    __syncthreads();

    float acc = l1b[j];
#pragma unroll 8
    for (int k = 0; k < HH; k++) acc = fmaf(row[k], l1W[k * HH + j], acc);
    h1[j] = fmaxf(acc, 0.f);
    __syncthreads();

    float acc2 = l2b[j];
#pragma unroll 8
    for (int k = 0; k < HH; k++) acc2 = fmaf(h1[k], l2W[k * HH + j], acc2);

    // log_softmax over 128 classes
    red[j] = acc2;
    __syncthreads();
    for (int s = 64; s > 0; s >>= 1) {
        if (j < s) red[j] = fmaxf(red[j], red[j + s]);
        __syncthreads();
    }
    float m = red[0];
    __syncthreads();
    red[j] = expf(acc2 - m);
    __syncthreads();
    for (int s = 64; s > 0; s >>= 1) {
        if (j < s) red[j] += red[j + s];
        __syncthreads();
    }
    float lse = m + logf(red[0]);
    out[g * HH + j] = acc2 - lse;
}

// ---------------------------------------------------------------------------
extern "C" void kernel_launch(void* const* d_in, const int* in_sizes, int n_in,
                              void* d_out, int out_size) {
    const float* x   = (const float*)d_in[0];
    const int*   ei  = (const int*)  d_in[1];
    const int*   n2s = (const int*)  d_in[2];
    const int*   s2g = (const int*)  d_in[3];
    const float* W1a = (const float*)d_in[4];
    const float* b1a = (const float*)d_in[5];
    const float* W1b = (const float*)d_in[6];
    const float* b1b = (const float*)d_in[7];
    const float* cWa = (const float*)d_in[8];
    const float* cba = (const float*)d_in[9];
    const float* cWb = (const float*)d_in[10];
    const float* cbb = (const float*)d_in[11];
    const float* l1W = (const float*)d_in[12];
    const float* l1b = (const float*)d_in[13];
    const float* l2W = (const float*)d_in[14];
    const float* l2b = (const float*)d_in[15];
    float* out = (float*)d_out;

    const int* src = ei;
    const int* dst = ei + EE;

    float *ph, *ph2, *pag, *psub, *pgr;
    cudaGetSymbolAddress((void**)&ph,   g_h);
    cudaGetSymbolAddress((void**)&ph2,  g_h2);
    cudaGetSymbolAddress((void**)&pag,  g_aggr);
    cudaGetSymbolAddress((void**)&psub, g_sub);
    cudaGetSymbolAddress((void**)&pgr,  g_graph);

    const int TB = 256;
    const int gemmBlocks = (NN + 63) / 64;

    // ---- conv1: F_IN=2 ----
    copy_f4<<<(NN * 2 / 4 + TB - 1) / TB, TB>>>((const float4*)x, (float4*)pag, NN * 2 / 4);
    edge_aggr2<<<(EE + TB - 1) / TB, TB>>>(src, dst, x, pag);
    conv1_lin<<<(NN * HH + TB - 1) / TB, TB>>>(pag, W1a, b1a, ph2);
    gemm_relu<<<gemmBlocks, TB>>>(ph2, W1b, b1b, ph);

    // ---- convs 2..4: H=128 ----
    for (int i = 0; i < 3; i++) {
        copy_f4<<<(NN * HH / 4 + TB - 1) / TB, TB>>>((const float4*)ph, (float4*)pag, NN * HH / 4);
        edge_aggr128<<<(EE * 32 + TB - 1) / TB, TB>>>(src, dst, ph, pag);
        gemm_relu<<<gemmBlocks, TB>>>(pag, cWa + i * HH * HH, cba + i * HH, ph2);
        gemm_relu<<<gemmBlocks, TB>>>(ph2, cWb + i * HH * HH, cbb + i * HH, ph);
    }

    // ---- nested pooling ----
    zero_f4<<<(SS * HH / 4 + TB - 1) / TB, TB>>>((float4*)psub, SS * HH / 4);
    pool_scatter<<<(NN * 32 + TB - 1) / TB, TB>>>(ph, n2s, psub, NN);
    zero_f4<<<(GG * HH / 4 + TB - 1) / TB, TB>>>((float4*)pgr, GG * HH / 4);
    pool_scatter<<<(SS * 32 + TB - 1) / TB, TB>>>(psub, s2g, pgr, SS);

    // ---- head ----
    head<<<GG, HH>>>(pgr, l1W, l1b, l2W, l2b, out);
}

// round 2
// speedup vs baseline: 2.3948x; 2.3948x over previous
#include <cuda_runtime.h>
#include <math.h>

#define NN 50000
#define EE 800000
#define HH 128
#define SS 5000
#define GG 64

// Scratch (device globals: no allocation allowed)
__device__ float g_h   [NN*HH];
__device__ float g_h2  [NN*HH];
__device__ float g_aggr[NN*HH];
__device__ float g_sub [SS*HH];
__device__ float g_graph[GG*HH];
__device__ int   g_rowptr[NN+1];
__device__ int   g_cur[NN];
__device__ int   g_csr[EE];
__device__ int   g_bsum[64];

// ---------------------------------------------------------------------------
// packed f32x2 helpers
__device__ __forceinline__ unsigned long long pack2(float lo, float hi) {
    unsigned long long r;
    asm("mov.b64 %0, {%1, %2};" : "=l"(r) : "f"(lo), "f"(hi));
    return r;
}
__device__ __forceinline__ unsigned long long fma2(unsigned long long a,
                                                   unsigned long long b,
                                                   unsigned long long c) {
    unsigned long long d;
    asm("fma.rn.f32x2 %0, %1, %2, %3;" : "=l"(d) : "l"(a), "l"(b), "l"(c));
    return d;
}
__device__ __forceinline__ float2 unpack2(unsigned long long v) {
    float2 f;
    asm("mov.b64 {%0, %1}, %2;" : "=f"(f.x), "=f"(f.y) : "l"(v));
    return f;
}

// ---------------------------------------------------------------------------
// CSR build: histogram -> scan -> bucket fill
__global__ void zero_int(int* __restrict__ p, int n) {
    int i = blockIdx.x * blockDim.x + threadIdx.x;
    if (i < n) p[i] = 0;
}

__global__ void hist_dst(const int* __restrict__ dst) {
    int e = blockIdx.x * blockDim.x + threadIdx.x;
    if (e < EE) atomicAdd(&g_rowptr[dst[e] + 1], 1);
}

// inclusive scan, 1024-wide blocks
__global__ void scan1(int* __restrict__ data, int* __restrict__ bsum, int n) {
    __shared__ int sh[1024];
    int gid = blockIdx.x * 1024 + threadIdx.x;
    int v = (gid < n) ? data[gid] : 0;
    sh[threadIdx.x] = v;
    __syncthreads();
    for (int off = 1; off < 1024; off <<= 1) {
        int t = (threadIdx.x >= off) ? sh[threadIdx.x - off] : 0;
        __syncthreads();
        sh[threadIdx.x] += t;
        __syncthreads();
    }
    if (gid < n) data[gid] = sh[threadIdx.x];
    if (threadIdx.x == 1023) bsum[blockIdx.x] = sh[1023];
}

// exclusive scan of block sums (nb <= 64)
__global__ void scan2(int* __restrict__ bsum, int nb) {
    __shared__ int sh[64];
    int i = threadIdx.x;
    int v = (i < nb) ? bsum[i] : 0;
    sh[i] = v;
    __syncthreads();
    for (int off = 1; off < 64; off <<= 1) {
        int t = (i >= off) ? sh[i - off] : 0;
        __syncthreads();
        sh[i] += t;
        __syncthreads();
    }
    if (i < nb) bsum[i] = sh[i] - v;  // exclusive
}

__global__ void scan3(int* __restrict__ data, const int* __restrict__ bsum, int n) {
    int gid = blockIdx.x * 1024 + threadIdx.x;
    if (gid < n) data[gid] += bsum[blockIdx.x];
}

__global__ void copy_cursor() {
    int i = blockIdx.x * blockDim.x + threadIdx.x;
    if (i < NN) g_cur[i] = g_rowptr[i];
}

__global__ void fill_csr(const int* __restrict__ src, const int* __restrict__ dst) {
    int e = blockIdx.x * blockDim.x + threadIdx.x;
    if (e >= EE) return;
    int d = dst[e];
    int pos = atomicAdd(&g_cur[d], 1);
    g_csr[pos] = src[e];
}

// ---------------------------------------------------------------------------
// conv1 aggregation (F_IN=2) via CSR gather: one thread per node
__global__ void aggr2_csr(const float* __restrict__ x, float* __restrict__ out) {
    int n = blockIdx.x * blockDim.x + threadIdx.x;
    if (n >= NN) return;
    float2 acc = *(const float2*)(x + 2 * n);
    int p = g_rowptr[n], e = g_rowptr[n + 1];
    for (; p < e; ++p) {
        int s = g_csr[p];
        float2 v = *(const float2*)(x + 2 * s);
        acc.x += v.x; acc.y += v.y;
    }
    *(float2*)(out + 2 * n) = acc;
}

// H=128 aggregation via CSR gather: one warp per node, 4 floats per lane.
// out[n] = h[n] + sum over incoming neighbors h[s].
__global__ void aggr128_csr(const float* __restrict__ h, float* __restrict__ out) {
    unsigned t = blockIdx.x * blockDim.x + threadIdx.x;
    unsigned n = t >> 5;
    if (n >= NN) return;
    int lane = (int)(t & 31);
    const float* hp = h + lane * 4;
    float4 acc = *(const float4*)(hp + (size_t)n * HH);
    int p = g_rowptr[n], e = g_rowptr[n + 1];
    for (; p + 3 < e; p += 4) {
        int s0 = g_csr[p], s1 = g_csr[p + 1], s2 = g_csr[p + 2], s3 = g_csr[p + 3];
        float4 v0 = *(const float4*)(hp + (size_t)s0 * HH);
        float4 v1 = *(const float4*)(hp + (size_t)s1 * HH);
        float4 v2 = *(const float4*)(hp + (size_t)s2 * HH);
        float4 v3 = *(const float4*)(hp + (size_t)s3 * HH);
        acc.x += (v0.x + v1.x) + (v2.x + v3.x);
        acc.y += (v0.y + v1.y) + (v2.y + v3.y);
        acc.z += (v0.z + v1.z) + (v2.z + v3.z);
        acc.w += (v0.w + v1.w) + (v2.w + v3.w);
    }
    for (; p < e; ++p) {
        int s = g_csr[p];
        float4 v = *(const float4*)(hp + (size_t)s * HH);
        acc.x += v.x; acc.y += v.y; acc.z += v.z; acc.w += v.w;
    }
    *(float4*)(out + (size_t)n * HH + lane * 4) = acc;
}

// ---------------------------------------------------------------------------
// conv1 first linear: (N,2) @ (2,128) + b, relu
__global__ void conv1_lin(const float* __restrict__ aggr2, const float* __restrict__ W1a,
                          const float* __restrict__ b1a, float* __restrict__ out) {
    int idx = blockIdx.x * blockDim.x + threadIdx.x;
    if (idx >= NN * HH) return;
    int n = idx >> 7, j = idx & 127;
    float a0 = aggr2[2 * n], a1 = aggr2[2 * n + 1];
    float v = fmaf(a0, W1a[j], fmaf(a1, W1a[HH + j], b1a[j]));
    out[idx] = fmaxf(v, 0.f);
}

// ---------------------------------------------------------------------------
// C[N,128] = relu(A[N,128] @ W[128,128] + bias), packed f32x2 FMA.
// Block: 256 threads, 128x128 tile; thread = 8 rows x 8 cols (4 f32x2 pairs).
__global__ void __launch_bounds__(256, 2)
gemm_relu(const float* __restrict__ A, const float* __restrict__ W,
          const float* __restrict__ bias, float* __restrict__ C) {
    __shared__ float As[16][128];   // k-major A tile
    __shared__ float Ws[16][128];   // k-major W tile

    const int tid = threadIdx.x;
    const int tm = tid >> 4;         // 0..15: rows tm*8..
    const int tn = tid & 15;         // 0..15: cols tn*8..
    const int rowBase = blockIdx.x * 128;

    unsigned long long acc[8][4];
#pragma unroll
    for (int i = 0; i < 8; i++)
#pragma unroll
        for (int j = 0; j < 4; j++) acc[i][j] = 0ull;

    const int lr = tid >> 1;          // 0..127: A row to load
    const int lk = (tid & 1) * 8;     // k offset 0 or 8
    const int wr = tid >> 5;          // 0..7: W row
    const int wc = (tid & 31) * 4;    // W col

    for (int k0 = 0; k0 < HH; k0 += 16) {
        float4 a0 = make_float4(0.f, 0.f, 0.f, 0.f), a1 = a0;
        int gr = rowBase + lr;
        if (gr < NN) {
            a0 = *(const float4*)(A + (size_t)gr * HH + k0 + lk);
            a1 = *(const float4*)(A + (size_t)gr * HH + k0 + lk + 4);
        }
        As[lk + 0][lr] = a0.x; As[lk + 1][lr] = a0.y;
        As[lk + 2][lr] = a0.z; As[lk + 3][lr] = a0.w;
        As[lk + 4][lr] = a1.x; As[lk + 5][lr] = a1.y;
        As[lk + 6][lr] = a1.z; As[lk + 7][lr] = a1.w;

        *(float4*)&Ws[wr][wc]     = *(const float4*)(W + (size_t)(k0 + wr) * HH + wc);
        *(float4*)&Ws[wr + 8][wc] = *(const float4*)(W + (size_t)(k0 + wr + 8) * HH + wc);
        __syncthreads();

#pragma unroll
        for (int kk = 0; kk < 16; kk++) {
            float4 av0 = *(const float4*)&As[kk][tm * 8];
            float4 av1 = *(const float4*)&As[kk][tm * 8 + 4];
            ulonglong2 wv0 = *(const ulonglong2*)&Ws[kk][tn * 8];      // (w0,w1),(w2,w3)
            ulonglong2 wv1 = *(const ulonglong2*)&Ws[kk][tn * 8 + 4];  // (w4,w5),(w6,w7)
            unsigned long long wp[4] = {wv0.x, wv0.y, wv1.x, wv1.y};
            float aa[8] = {av0.x, av0.y, av0.z, av0.w, av1.x, av1.y, av1.z, av1.w};
            unsigned long long ap[8];
#pragma unroll
            for (int i = 0; i < 8; i++) ap[i] = pack2(aa[i], aa[i]);
#pragma unroll
            for (int i = 0; i < 8; i++)
#pragma unroll
                for (int j = 0; j < 4; j++)
                    acc[i][j] = fma2(ap[i], wp[j], acc[i][j]);
        }
        __syncthreads();
    }

    float4 b0 = *(const float4*)(bias + tn * 8);
    float4 b1 = *(const float4*)(bias + tn * 8 + 4);
    float bb[8] = {b0.x, b0.y, b0.z, b0.w, b1.x, b1.y, b1.z, b1.w};
#pragma unroll
    for (int i = 0; i < 8; i++) {
        int row = rowBase + tm * 8 + i;
        if (row < NN) {
            float o[8];
#pragma unroll
            for (int j = 0; j < 4; j++) {
                float2 f = unpack2(acc[i][j]);
                o[2 * j]     = fmaxf(f.x + bb[2 * j], 0.f);
                o[2 * j + 1] = fmaxf(f.y + bb[2 * j + 1], 0.f);
            }
            *(float4*)(C + (size_t)row * HH + tn * 8)     = make_float4(o[0], o[1], o[2], o[3]);
            *(float4*)(C + (size_t)row * HH + tn * 8 + 4) = make_float4(o[4], o[5], o[6], o[7]);
        }
    }
}

// ---------------------------------------------------------------------------
__global__ void zero_f4(float4* __restrict__ d, int n4) {
    int i = blockIdx.x * blockDim.x + threadIdx.x;
    if (i < n4) d[i] = make_float4(0.f, 0.f, 0.f, 0.f);
}

// Segment-sum scatter: one warp per input row, 4 floats per lane.
__global__ void pool_scatter(const float* __restrict__ h, const int* __restrict__ seg,
                             float* __restrict__ out, int n) {
    unsigned t = blockIdx.x * blockDim.x + threadIdx.x;
    unsigned i = t >> 5;
    if (i >= (unsigned)n) return;
    int lane = (int)(t & 31);
    int sg = seg[i];
    float4 v = *(const float4*)(h + (size_t)i * HH + lane * 4);
    float* o = out + (size_t)sg * HH + lane * 4;
    atomicAdd(o + 0, v.x);
    atomicAdd(o + 1, v.y);
    atomicAdd(o + 2, v.z);
    atomicAdd(o + 3, v.w);
}

// Head: per-graph MLP + log_softmax. One block per graph, 128 threads.
__global__ void head(const float* __restrict__ graph, const float* __restrict__ l1W,
                     const float* __restrict__ l1b, const float* __restrict__ l2W,
                     const float* __restrict__ l2b, float* __restrict__ out) {
    __shared__ float row[HH];
    __shared__ float h1[HH];
    __shared__ float red[HH];
    int g = blockIdx.x;
    int j = threadIdx.x;

    row[j] = graph[g * HH + j];
    __syncthreads();

    float acc = l1b[j];
#pragma unroll 8
    for (int k = 0; k < HH; k++) acc = fmaf(row[k], l1W[k * HH + j], acc);
    h1[j] = fmaxf(acc, 0.f);
    __syncthreads();

    float acc2 = l2b[j];
#pragma unroll 8
    for (int k = 0; k < HH; k++) acc2 = fmaf(h1[k], l2W[k * HH + j], acc2);

    red[j] = acc2;
    __syncthreads();
    for (int s = 64; s > 0; s >>= 1) {
        if (j < s) red[j] = fmaxf(red[j], red[j + s]);
        __syncthreads();
    }
    float m = red[0];
    __syncthreads();
    red[j] = expf(acc2 - m);
    __syncthreads();
    for (int s = 64; s > 0; s >>= 1) {
        if (j < s) red[j] += red[j + s];
        __syncthreads();
    }
    float lse = m + logf(red[0]);
    out[g * HH + j] = acc2 - lse;
}

// ---------------------------------------------------------------------------
extern "C" void kernel_launch(void* const* d_in, const int* in_sizes, int n_in,
                              void* d_out, int out_size) {
    const float* x   = (const float*)d_in[0];
    const int*   ei  = (const int*)  d_in[1];
    const int*   n2s = (const int*)  d_in[2];
    const int*   s2g = (const int*)  d_in[3];
    const float* W1a = (const float*)d_in[4];
    const float* b1a = (const float*)d_in[5];
    const float* W1b = (const float*)d_in[6];
    const float* b1b = (const float*)d_in[7];
    const float* cWa = (const float*)d_in[8];
    const float* cba = (const float*)d_in[9];
    const float* cWb = (const float*)d_in[10];
    const float* cbb = (const float*)d_in[11];
    const float* l1W = (const float*)d_in[12];
    const float* l1b = (const float*)d_in[13];
    const float* l2W = (const float*)d_in[14];
    const float* l2b = (const float*)d_in[15];
    float* out = (float*)d_out;

    const int* src = ei;
    const int* dst = ei + EE;

    float *ph, *ph2, *pag, *psub, *pgr;
    int *prp, *pbs;
    cudaGetSymbolAddress((void**)&ph,   g_h);
    cudaGetSymbolAddress((void**)&ph2,  g_h2);
    cudaGetSymbolAddress((void**)&pag,  g_aggr);
    cudaGetSymbolAddress((void**)&psub, g_sub);
    cudaGetSymbolAddress((void**)&pgr,  g_graph);
    cudaGetSymbolAddress((void**)&prp,  g_rowptr);
    cudaGetSymbolAddress((void**)&pbs,  g_bsum);

    const int TB = 256;
    const int gemmBlocks = (NN + 127) / 128;
    const int nScan = NN + 1;
    const int scanBlocks = (nScan + 1023) / 1024;  // 49

    // ---- CSR build ----
    zero_int<<<(nScan + TB - 1) / TB, TB>>>(prp, nScan);
    hist_dst<<<(EE + TB - 1) / TB, TB>>>(dst);
    scan1<<<scanBlocks, 1024>>>(prp, pbs, nScan);
    scan2<<<1, 64>>>(pbs, scanBlocks);
    scan3<<<scanBlocks, 1024>>>(prp, pbs, nScan);
    copy_cursor<<<(NN + TB - 1) / TB, TB>>>();
    fill_csr<<<(EE + TB - 1) / TB, TB>>>(src, dst);

    // ---- conv1: F_IN=2 ----
    aggr2_csr<<<(NN + TB - 1) / TB, TB>>>(x, pag);
    conv1_lin<<<(NN * HH + TB - 1) / TB, TB>>>(pag, W1a, b1a, ph2);
    gemm_relu<<<gemmBlocks, TB>>>(ph2, W1b, b1b, ph);

    // ---- convs 2..4: H=128 ----
    for (int i = 0; i < 3; i++) {
        aggr128_csr<<<(NN * 32 + TB - 1) / TB, TB>>>(ph, pag);
        gemm_relu<<<gemmBlocks, TB>>>(pag, cWa + i * HH * HH, cba + i * HH, ph2);
        gemm_relu<<<gemmBlocks, TB>>>(ph2, cWb + i * HH * HH, cbb + i * HH, ph);
    }

    // ---- nested pooling ----
    zero_f4<<<(SS * HH / 4 + TB - 1) / TB, TB>>>((float4*)psub, SS * HH / 4);
    pool_scatter<<<(NN * 32 + TB - 1) / TB, TB>>>(ph, n2s, psub, NN);
    zero_f4<<<(GG * HH / 4 + TB - 1) / TB, TB>>>((float4*)pgr, GG * HH / 4);
    pool_scatter<<<(SS * 32 + TB - 1) / TB, TB>>>(psub, s2g, pgr, SS);

    // ---- head ----
    head<<<GG, HH>>>(pgr, l1W, l1b, l2W, l2b, out);
}